// round 12
// baseline (speedup 1.0000x reference)
#include <cuda_runtime.h>

// Float32HardwareSurrogate — warp-shuffle, SEL-free reduce-scatter, with
// deferred stage-2 tail: a 4x4 cross-lane transpose every 4 images replaces
// the per-image xor2/xor1 reduce (8->7 SHFL/image) and turns 4 predicated
// 32-bit store wavefronts into ONE fully-coalesced 128B store.
//
// Data layout: coalesced float4 loads (idx = lane + 32k) put one complete
// image per 16-lane group per iteration: lane e holds float4 element e of
// image 2k+(lane>>4). Element e -> quadrant q=((e>>3)<<1)|(e&1), quadrant-row
// rr=(e>>1)&3.
// Stage 1: partial over 4 conv channels; reduce-scatter (xor4 x2, xor2)
// leaves lane e with scalar c[K], K=q*4+rr.
// Stage 2: T=clip(relu(c)/64)*Wl[K]; reduce-scatter xor8 x2, xor4 leaves a
// partial sc_k per lane; partials for iterations 4kb..4kb+3 are collected in
// registers and transposed across lane bits 0-1, after which lane e holds all
// 4 partials of iteration 4kb+(e&3) -> local sum, scale, clip, store.
// Weights are pre-permuted per lane (pos p = channel rr^p / output ncomp^p)
// so scatter steps are unconditionally keep(x,y)/send(z,w).

#define THREADS 256
#define WARPS_PER_BLOCK 8
#define IMGS_PER_WARP 32

// XOR-permute float4 components: result pos p = w[bits ^ p]. Prologue-only.
__device__ __forceinline__ float4 xorperm(float4 w, int bits) {
    float t;
    if (bits & 2) { t = w.x; w.x = w.z; w.z = t; t = w.y; w.y = w.w; w.w = t; }
    if (bits & 1) { t = w.x; w.x = w.y; w.y = t; t = w.z; w.z = w.w; w.w = t; }
    return w;
}

__global__ void __launch_bounds__(THREADS, 5)   // 51-reg cap -> 40 warps/SM
surrogate_kernel(const float* __restrict__ img1,
                 const float* __restrict__ img2,
                 const float* __restrict__ Wc,
                 const float* __restrict__ Wl,
                 float* __restrict__ out,
                 int nimg)
{
    const int lane = threadIdx.x & 31;
    const int warp = threadIdx.x >> 5;
    const long wg  = (long)blockIdx.x * WARPS_PER_BLOCK + warp;
    const long g0  = wg * IMGS_PER_WARP;
    const long total = 2L * (long)nimg;
    if (g0 >= total) return;

    // nimg is a multiple of 32 -> warp never straddles img1/img2.
    const float4* __restrict__ src = (const float4*)(
        (g0 < (long)nimg) ? (img1 + g0 * 64)
                          : (img2 + (g0 - (long)nimg) * 64));

    const int e     = lane & 15;
    const int g     = lane >> 4;
    const int rr    = (e >> 1) & 3;
    const int q     = ((e >> 3) << 1) | (e & 1);
    const int K     = q * 4 + rr;
    const int ncomp = 2 * ((e >> 3) & 1) + ((e >> 2) & 1);

    // Vector weight loads + one-time per-lane XOR permutation.
    const float4* __restrict__ Wc4 = (const float4*)Wc;
    const float4* __restrict__ Wl4 = (const float4*)Wl;
    const float4 wc0 = xorperm(Wc4[rr * 4 + 0], rr);
    const float4 wc1 = xorperm(Wc4[rr * 4 + 1], rr);
    const float4 wc2 = xorperm(Wc4[rr * 4 + 2], rr);
    const float4 wc3 = xorperm(Wc4[rr * 4 + 3], rr);
    const float4 wl  = xorperm(Wl4[K], ncomp);

    const float inv64 = 0.015625f;
    const unsigned FULL = 0xffffffffu;

    // Per-group store base: lane e stores component ncomp of image
    // g0 + 8*kb + 2*(e&3) + g  ->  32 lanes cover one contiguous 128B line.
    float* __restrict__ outq = out + (g0 + 2 * (e & 3) + g) * 4 + ncomp;

    // Ring software pipeline, window 4.
    float4 v[4];
    #pragma unroll
    for (int k = 0; k < 4; ++k)
        v[k] = __ldcs(&src[lane + 32 * k]);

    const bool p1 = (lane & 1);
    const bool p2 = (lane & 2);

    #pragma unroll
    for (int kb = 0; kb < 4; ++kb) {
        float s[4];
        #pragma unroll
        for (int j = 0; j < 4; ++j) {
            const int k = kb * 4 + j;
            float4 cur = v[k & 3];
            if (k < 12)
                v[k & 3] = __ldcs(&src[lane + 32 * (k + 4)]);

            // Stage 1 partials (position p = channel rr^p)
            float4 P;
            P.x = cur.x * wc0.x; P.y = cur.x * wc0.y;
            P.z = cur.x * wc0.z; P.w = cur.x * wc0.w;
            P.x = fmaf(cur.y, wc1.x, P.x); P.y = fmaf(cur.y, wc1.y, P.y);
            P.z = fmaf(cur.y, wc1.z, P.z); P.w = fmaf(cur.y, wc1.w, P.w);
            P.x = fmaf(cur.z, wc2.x, P.x); P.y = fmaf(cur.z, wc2.y, P.y);
            P.z = fmaf(cur.z, wc2.z, P.z); P.w = fmaf(cur.z, wc2.w, P.w);
            P.x = fmaf(cur.w, wc3.x, P.x); P.y = fmaf(cur.w, wc3.y, P.y);
            P.z = fmaf(cur.w, wc3.z, P.z); P.w = fmaf(cur.w, wc3.w, P.w);

            float A  = P.x + __shfl_xor_sync(FULL, P.z, 4);
            float Bv = P.y + __shfl_xor_sync(FULL, P.w, 4);
            float c1 = A   + __shfl_xor_sync(FULL, Bv,  2);
            float cv = fminf(fmaxf(c1, 0.0f) * inv64, 127.0f);

            // Stage 2 partials (position p = output ncomp^p)
            float Tx = cv * wl.x, Ty = cv * wl.y;
            float Tz = cv * wl.z, Tw = cv * wl.w;
            float A2 = Tx + __shfl_xor_sync(FULL, Tz, 8);
            float B2 = Ty + __shfl_xor_sync(FULL, Tw, 8);
            s[j] = A2 + __shfl_xor_sync(FULL, B2, 4);   // partial: needs sum
        }                                               // over lane bits 0-1

        // 4x4 transpose across lane bits 0-1 (columns = iterations).
        // Stage xor1: swap within 2x2 diagonal blocks.
        {
            float t0 = p1 ? s[0] : s[1];
            float t1 = p1 ? s[2] : s[3];
            float r0 = __shfl_xor_sync(FULL, t0, 1);
            float r1 = __shfl_xor_sync(FULL, t1, 1);
            if (p1) { s[0] = r0; s[2] = r1; }
            else    { s[1] = r0; s[3] = r1; }
        }
        // Stage xor2: swap off-diagonal 2x2 blocks.
        {
            float t0 = p2 ? s[0] : s[2];
            float t1 = p2 ? s[1] : s[3];
            float r0 = __shfl_xor_sync(FULL, t0, 2);
            float r1 = __shfl_xor_sync(FULL, t1, 2);
            if (p2) { s[0] = r0; s[1] = r1; }
            else    { s[2] = r0; s[3] = r1; }
        }

        // Lane e now holds the 4 partials of iteration kb*4 + (e&3).
        float sc = (s[0] + s[1]) + (s[2] + s[3]);
        float o  = fminf(fmaxf(sc * inv64, -128.0f), 127.0f);

        // All 32 lanes store: one contiguous 128B line (8 images x 4 comps).
        __stcs(outq + 32 * kb, o);
    }
}

extern "C" void kernel_launch(void* const* d_in, const int* in_sizes, int n_in,
                              void* d_out, int out_size) {
    const float* img1 = (const float*)d_in[0];
    const float* img2 = (const float*)d_in[1];
    const float* Wc   = (const float*)d_in[2];
    const float* Wl   = (const float*)d_in[3];
    float* out        = (float*)d_out;

    int nimg = in_sizes[0] / 64;                       // B
    long total_imgs = 2L * (long)nimg;
    long total_warps = (total_imgs + IMGS_PER_WARP - 1) / IMGS_PER_WARP;
    int nblocks = (int)((total_warps + WARPS_PER_BLOCK - 1) / WARPS_PER_BLOCK);

    surrogate_kernel<<<nblocks, THREADS>>>(img1, img2, Wc, Wl, out, nimg);
}